// round 17
// baseline (speedup 1.0000x reference)
#include <cuda_runtime.h>
#include <cuda_fp16.h>
#include <mma.h>
#include <cstdint>

// UpConvBlock: y = ConvTranspose2d(x, w1, k=4, s=2, p=1) + b1
//              out = PAC-3x3(y, guide, w2) + b2
// R17: B staging via cp.async (async engine, no LDG->STS issue chain).
// Three shifted fp16 copies of padded x and y (16B-aligned rows) so every
// tap is a 16B cp.async. pac does an in-place k-multiply on its OWN cp.async
// data (no extra barrier). 4 CTAs/SM preserved.

#define H1 64
#define W1 64
#define CIN 256
#define CMID 128
#define H2 128
#define W2 128
#define BATCH 4

#define XP_H 66
#define XP_W 72                      // 144B rows (16B multiple)
#define XP_CH (XP_H * XP_W)          // 4752
#define YP_H 130
#define YP_W 136                     // 272B rows (16B multiple)
#define YP_CH (YP_H * YP_W)          // 17680

typedef unsigned long long u64;
typedef unsigned int u32;

using namespace nvcuda;

__device__ __forceinline__ u32 smem_u32(const void* p) {
    u32 a; asm("{ .reg .u64 t; cvta.to.shared.u64 t, %1; cvt.u32.u64 %0, t; }" : "=r"(a) : "l"(p));
    return a;
}
__device__ __forceinline__ void cpasync16(u32 dst, const void* src) {
    asm volatile("cp.async.ca.shared.global [%0], [%1], 16;" :: "r"(dst), "l"(src));
}
__device__ __forceinline__ void cpasync_wait() {
    asm volatile("cp.async.commit_group;\n\tcp.async.wait_group 0;" ::: "memory");
}

// ---------------- scratch globals ----------------
__device__ __align__(16) __half g_xS[3][BATCH * CIN * XP_CH];   // shifts 0/1/2
__device__ __align__(16) __half g_yS[3][BATCH * CMID * YP_CH];  // shifts 0/1/2
__device__ __align__(128) __half g_w1[4 * 8 * 128 * 128];       // [par][kc][o][krow]
__device__ __align__(128) __half g_w2[9 * 128 * 128];           // [ij][o][c]

// smem: A [128][136] halves, B [128][72] halves (144B rows, 16B aligned)
#define SA2 136
#define SB 72
#define OFF_A 0
#define OFF_B 34816
#define KS32 16384                       // pac phase A: fp32 [9][64] (A region)
#define OFF_KSH 53248                    // pac: half2 [9][32]
#define CONVT_SMEM 53248
#define PAC_SMEM   54400

// ---------------------------------------------------------------------------
// Prep kernels
// ---------------------------------------------------------------------------
#define NW1 (4 * 8 * 128 * 128)
#define NW2 (9 * 128 * 128)

__global__ void prep_w(const float* __restrict__ w1, const float* __restrict__ w2) {
    int idx = blockIdx.x * 256 + threadIdx.x;
    if (idx < NW1) {
        int kr = idx & 127;
        int o  = (idx >> 7) & 127;
        int kc = (idx >> 14) & 7;
        int par = idx >> 17;
        int di = par >> 1, dj = par & 1;
        int c = kc * 32 + (kr >> 2);
        int tap = kr & 3;
        int t = tap >> 1, u = tap & 1;
        g_w1[idx] = __float2half_rn(w1[(c * CMID + o) * 16 + (3 - di - 2 * t) * 4 + (3 - dj - 2 * u)]);
    } else if (idx < NW1 + NW2) {
        int k = idx - NW1;
        int c  = k & 127;
        int o  = (k >> 7) & 127;
        int ij = k >> 14;
        int i = ij / 3, j = ij % 3;
        g_w2[k] = __float2half_rn(w2[(c * CMID + o) * 9 + (2 - i) * 3 + (2 - j)]);
    }
}

__global__ void pad_xk(const float* __restrict__ x) {
    int idx = blockIdx.x * 256 + threadIdx.x;        // BATCH*CIN*XP_CH
    if (idx >= BATCH * CIN * XP_CH) return;
    int col = idx % XP_W;
    int r   = (idx / XP_W) % XP_H;
    int bc  = idx / XP_CH;
    int h = r - 1;
    bool okh = (unsigned)h < (unsigned)H1;
#pragma unroll
    for (int s = 0; s < 3; s++) {
        int w = col - 1 + s;
        float v = (okh && (unsigned)w < (unsigned)W1) ? x[bc * (H1 * W1) + h * W1 + w] : 0.f;
        g_xS[s][idx] = __float2half_rn(v);
    }
}

// zero only the frame cells of the 3 y copies that pac can read.
// copy s: rows 0 & 129 (all 136 cols), and col (129-s) rows 1..128.
__global__ void pad_y_border() {
    int idx = blockIdx.x * 256 + threadIdx.x;        // 512 * 1200
    if (idx >= BATCH * CMID * 1200) return;
    int e  = idx % 1200;
    int bo = idx / 1200;
    int s  = e / 400;
    int e2 = e % 400;
    __half* base = g_yS[s] + (u64)bo * YP_CH;
    __half z = __float2half_rn(0.f);
    if (e2 < 136)       base[e2] = z;
    else if (e2 < 272)  base[129 * YP_W + (e2 - 136)] = z;
    else                base[(1 + (e2 - 272)) * YP_W + (129 - s)] = z;
}

// ---------------------------------------------------------------------------
// MMA stage: A[128][136], B[128][72], 8 k-steps.
// ---------------------------------------------------------------------------
template<typename AccT>
__device__ __forceinline__ void mma_stage(const char* smem, int mo, int np, AccT (&acc)[2][2]) {
#pragma unroll
    for (int k0 = 0; k0 < 8; k0++) {
        const __half* B = (const __half*)(smem + OFF_B);
        const __half* A = (const __half*)(smem + OFF_A);
        wmma::fragment<wmma::matrix_b, 16, 16, 16, __half, wmma::row_major> bf[2];
        wmma::fragment<wmma::matrix_a, 16, 16, 16, __half, wmma::row_major> af[2];
        wmma::load_matrix_sync(bf[0], B + (k0 * 16) * SB + np, SB);
        wmma::load_matrix_sync(bf[1], B + (k0 * 16) * SB + np + 16, SB);
        wmma::load_matrix_sync(af[0], A + mo * SA2 + k0 * 16, SA2);
        wmma::load_matrix_sync(af[1], A + (mo + 16) * SA2 + k0 * 16, SA2);
#pragma unroll
        for (int m = 0; m < 2; m++)
#pragma unroll
            for (int n = 0; n < 2; n++)
                wmma::mma_sync(acc[m][n], af[m], bf[n], acc[m][n]);
    }
}

// ---------------------------------------------------------------------------
// Kernel 1: conv_transpose (parity decomposition). Block: 128o x 64px.
// K = 1024 in 8 chunks of 128 (32c x 4taps). B staging = pure cp.async.
// Item map: krow = (tid>>3) + 32q, rchunk = tid&7 (16B = 8 px of one r-row).
// ---------------------------------------------------------------------------
__global__ __launch_bounds__(256, 4) void convt_wmma(const float* __restrict__ b1) {
    extern __shared__ __align__(128) char smem[];
    const u32 sb = smem_u32(smem);
    const int tid = threadIdx.x;
    const int wid = tid >> 5;
    const int mo = (wid & 3) * 32;
    const int np = (wid >> 2) * 32;

    const int bz = blockIdx.z;
    const int b  = bz >> 2;
    const int par = bz & 3;
    const int di = par >> 1, dj = par & 1;
    const int i0 = blockIdx.y * 8;
    const int j0 = blockIdx.x * 8;

    // per-thread cp.async coords (q-invariant except channel += 8 per q)
    const int rch = tid & 7;                 // r-row chunk
    const int tap = (tid >> 3) & 3;
    const int t = tap >> 1, u = tap & 1;
    const int shift = dj + u;                // 0..2 -> x copy select
    const __half* xbase = g_xS[shift] + ((u64)(b * CIN + (tid >> 5)) * XP_CH)
                        + (i0 + di + rch + t) * XP_W + j0;
    const u32 bdst = sb + OFF_B + (u32)((tid >> 3) * (SB * 2) + rch * 16);

    wmma::fragment<wmma::accumulator, 16, 16, 16, float> acc[2][2];
#pragma unroll
    for (int m = 0; m < 2; m++)
#pragma unroll
        for (int n = 0; n < 2; n++) wmma::fill_fragment(acc[m][n], 0.f);

    for (int kc = 0; kc < 8; kc++) {
        __syncthreads();
        // A weights
        {
            const __half* wA = g_w1 + (par * 8 + kc) * 16384;
#pragma unroll
            for (int q = 0; q < 8; q++) {
                int p = tid + q * 256;
                int o = p >> 4, ch = p & 15;
                cpasync16(sb + OFF_A + (u32)(o * (SA2 * 2) + ch * 16), wA + o * 128 + ch * 8);
            }
        }
        // B activations: 4 x 16B per thread, channel stride 8 per q
        const __half* xs = xbase + (u64)(kc * 32) * XP_CH;
#pragma unroll
        for (int q = 0; q < 4; q++)
            cpasync16(bdst + q * (32 * SB * 2), xs + (u64)(8 * q) * XP_CH);
        cpasync_wait();
        __syncthreads();

        mma_stage(smem, mo, np, acc);
    }

    // epilogue: fbuf [128][72] fp32, parity scatter into 3 fp16 y copies
    __syncthreads();
    float* fbuf = (float*)smem;
#pragma unroll
    for (int m = 0; m < 2; m++)
#pragma unroll
        for (int n = 0; n < 2; n++)
            wmma::store_matrix_sync(fbuf + (mo + m * 16) * SB + np + n * 16,
                                    acc[m][n], SB, wmma::mem_row_major);
    __syncthreads();
    for (int idx = tid; idx < 8192; idx += 256) {
        int o = idx >> 6;
        int n = idx & 63;
        int rr = n >> 3, cc = n & 7;
        float v = fbuf[o * SB + n] + __ldg(&b1[o]);
        __half hv = __float2half_rn(v);
        u64 base = (u64)(b * CMID + o) * YP_CH
                 + (2 * (i0 + rr) + di + 1) * YP_W + 2 * (j0 + cc) + dj + 1;
        g_yS[0][base] = hv;
        g_yS[1][base - 1] = hv;
        g_yS[2][base - 2] = hv;       // col-2 may land in unread pad; in-array
    }
}

// ---------------------------------------------------------------------------
// Kernel 2: PAC 3x3. Block: 128o x 64px. 9 ij stages, K=128 each.
// B: cp.async raw y (copy j), then in-place k-multiply on OWN data
// (cp.async dst map == multiply map -> wait_group 0 suffices, no barrier).
// ---------------------------------------------------------------------------
__global__ __launch_bounds__(256, 4) void pac_wmma(const float* __restrict__ guide,
                                                   const float* __restrict__ b2,
                                                   float* __restrict__ out) {
    extern __shared__ __align__(128) char smem[];
    const u32 sb = smem_u32(smem);
    const int tid = threadIdx.x;
    const int wid = tid >> 5;
    const int mo = (wid & 3) * 32;
    const int np = (wid >> 2) * 32;

    const int b  = blockIdx.z;
    const int h0 = blockIdx.y * 8;
    const int w0 = blockIdx.x * 8;

    float* ks32 = (float*)(smem + KS32);
    u32*   ksh  = (u32*)(smem + OFF_KSH);
    float* gs   = (float*)smem;

    // ---- Phase A: guide kernel ----
    for (int tt = tid; tt < 576; tt += 256) ks32[tt] = 0.f;

    for (int cc = 0; cc < CMID; cc += 32) {
        __syncthreads();
        for (int idx = tid; idx < 3200; idx += 256) {
            int c = idx / 100;
            int rr = (idx % 100) / 10;
            int col = idx % 10;
            int gh = h0 - 1 + rr, gw = w0 - 1 + col;
            float v = 0.f;
            if ((unsigned)gh < (unsigned)H2 && (unsigned)gw < (unsigned)W2)
                v = guide[((b * CMID + cc + c) * H2 + gh) * W2 + gw];
            gs[c * 120 + rr * 12 + col] = v;
        }
        __syncthreads();
        for (int idx = tid; idx < 576; idx += 256) {
            int ij = idx >> 6;
            int p  = idx & 63;
            int i = ij / 3, j = ij % 3;
            int rr = p >> 3, cww = p & 7;
            float s = 0.f;
#pragma unroll
            for (int c = 0; c < 32; c++) {
                float d = gs[c * 120 + (rr + i) * 12 + (cww + j)] - gs[c * 120 + (rr + 1) * 12 + (cww + 1)];
                s += d * d;
            }
            ks32[idx] += s;
        }
    }
    __syncthreads();
    for (int tt = tid; tt < 576; tt += 256) ks32[tt] = __expf(-0.5f * ks32[tt]);
    __syncthreads();
    for (int tt = tid; tt < 288; tt += 256) {
        int ij = tt >> 5, p = tt & 31;
        __half2 hk = __floats2half2_rn(ks32[ij * 64 + 2 * p], ks32[ij * 64 + 2 * p + 1]);
        ksh[tt] = *(u32*)&hk;
    }
    __syncthreads();

    // ---- Phase B: 9 ij stages ----
    const int rch = tid & 7;                 // r-row chunk (16B = 8 px)
    const u64 yoff0 = (u64)(b * CMID + (tid >> 3)) * YP_CH + (h0 + rch) * YP_W + w0;
    const u32 bdst = sb + OFF_B + (u32)((tid >> 3) * (SB * 2) + rch * 16);
    char* bgen = smem + OFF_B + (tid >> 3) * (SB * 2) + rch * 16;

    wmma::fragment<wmma::accumulator, 16, 16, 16, float> acc[2][2];
#pragma unroll
    for (int m = 0; m < 2; m++)
#pragma unroll
        for (int n = 0; n < 2; n++) wmma::fill_fragment(acc[m][n], 0.f);

    for (int ij = 0; ij < 9; ij++) {
        const int i = ij / 3, j = ij % 3;
        __syncthreads();
        // A weights
        {
            const __half* wA = g_w2 + ij * 16384;
#pragma unroll
            for (int q = 0; q < 8; q++) {
                int p = tid + q * 256;
                int o = p >> 4, ch = p & 15;
                cpasync16(sb + OFF_A + (u32)(o * (SA2 * 2) + ch * 16), wA + o * 128 + ch * 8);
            }
        }
        // B raw y: 4 x 16B per thread (channel += 32 per q)
        const __half* ys = g_yS[j] + yoff0 + i * YP_W;
#pragma unroll
        for (int q = 0; q < 4; q++)
            cpasync16(bdst + q * (32 * SB * 2), ys + (u64)(32 * q) * YP_CH);
        cpasync_wait();
        // in-place k-multiply on this thread's own 4 x 16B
        uint4 kv = *(const uint4*)&ksh[ij * 32 + 4 * rch];
        const __half2 k0 = *(const __half2*)&kv.x;
        const __half2 k1 = *(const __half2*)&kv.y;
        const __half2 k2 = *(const __half2*)&kv.z;
        const __half2 k3 = *(const __half2*)&kv.w;
#pragma unroll
        for (int q = 0; q < 4; q++) {
            uint4 v = *(uint4*)(bgen + q * (32 * SB * 2));
            __half2 a0 = __hmul2(*(const __half2*)&v.x, k0);
            __half2 a1 = __hmul2(*(const __half2*)&v.y, k1);
            __half2 a2 = __hmul2(*(const __half2*)&v.z, k2);
            __half2 a3 = __hmul2(*(const __half2*)&v.w, k3);
            uint4 o4;
            o4.x = *(u32*)&a0; o4.y = *(u32*)&a1; o4.z = *(u32*)&a2; o4.w = *(u32*)&a3;
            *(uint4*)(bgen + q * (32 * SB * 2)) = o4;
        }
        __syncthreads();

        mma_stage(smem, mo, np, acc);
    }

    // ---- Epilogue ----
    __syncthreads();
    float* fbuf = (float*)smem;
#pragma unroll
    for (int m = 0; m < 2; m++)
#pragma unroll
        for (int n = 0; n < 2; n++)
            wmma::store_matrix_sync(fbuf + (mo + m * 16) * SB + np + n * 16,
                                    acc[m][n], SB, wmma::mem_row_major);
    __syncthreads();
    for (int idx = tid; idx < 8192; idx += 256) {
        int o = idx >> 6;
        int n = idx & 63;
        float v = fbuf[o * SB + n] + __ldg(&b2[o]);
        out[((b * CMID + o) * H2 + h0 + (n >> 3)) * W2 + w0 + (n & 7)] = v;
    }
}

extern "C" void kernel_launch(void* const* d_in, const int* in_sizes, int n_in,
                              void* d_out, int out_size) {
    const float* x     = (const float*)d_in[0];
    const float* guide = (const float*)d_in[1];
    const float* w1    = (const float*)d_in[2];
    const float* b1    = (const float*)d_in[3];
    const float* w2    = (const float*)d_in[4];
    const float* b2    = (const float*)d_in[5];
    float* out = (float*)d_out;

    cudaFuncSetAttribute(convt_wmma, cudaFuncAttributeMaxDynamicSharedMemorySize, CONVT_SMEM);
    cudaFuncSetAttribute(pac_wmma, cudaFuncAttributeMaxDynamicSharedMemorySize, PAC_SMEM);

    prep_w<<<(NW1 + NW2 + 255) / 256, 256>>>(w1, w2);
    pad_xk<<<(BATCH * CIN * XP_CH + 255) / 256, 256>>>(x);
    pad_y_border<<<(BATCH * CMID * 1200 + 255) / 256, 256>>>();
    convt_wmma<<<dim3(8, 8, BATCH * 4), 256, CONVT_SMEM>>>(b1);
    pac_wmma<<<dim3(16, 16, BATCH), 256, PAC_SMEM>>>(guide, b2, out);
}